// round 16
// baseline (speedup 1.0000x reference)
#include <cuda_runtime.h>
#include <math.h>

#define B_  64
#define T_  1024
#define I_  256
#define H_  512
#define G_  2048          // 4*H
#define BH_ (B_*H_)       // 32768
#define BG_ (B_*G_)       // 131072

// ---------------- scratch (device globals; no allocation allowed) ----------------
__device__ float g_Wih[G_*H_];              // permuted input weights (gate-interleaved rows), max K=512
__device__ float g_Whh[G_*H_];              // permuted recurrent weights
__device__ float g_bias[G_];                // b_ih + b_hh, permuted
__device__ float g_xp[(size_t)T_*B_*G_];    // precomputed x@W_ih + bias, layout [t][b][g']
__device__ float g_y0[(size_t)T_*B_*H_];    // layer-0 outputs, layout [t][b][h]
__device__ float g_h[2][BH_];               // h ping-pong
__device__ unsigned g_arrive;               // grid-barrier cumulative arrivals
__device__ unsigned g_release;              // grid-barrier release step

__device__ __forceinline__ float tanh_ap(float x) {
    float y; asm("tanh.approx.f32 %0, %1;" : "=f"(y) : "f"(x)); return y;
}
__device__ __forceinline__ float sig_ap(float x) {
    return 0.5f * tanh_ap(0.5f * x) + 0.5f;
}

// ---------------- weight permutation: g' = 4*j + gate  <-  g = gate*H + j ----------------
__global__ void permute_kernel(const float* __restrict__ Wih,
                               const float* __restrict__ Whh,
                               const float* __restrict__ bih,
                               const float* __restrict__ bhh,
                               int Kin) {
    int total = G_*Kin + G_*H_ + G_;
    for (int e = blockIdx.x*blockDim.x + threadIdx.x; e < total; e += gridDim.x*blockDim.x) {
        if (e < G_*Kin) {
            int gp = e / Kin, col = e - gp*Kin;
            int j = gp >> 2, q = gp & 3;
            g_Wih[gp*Kin + col] = Wih[(q*H_ + j)*Kin + col];
        } else if (e < G_*Kin + G_*H_) {
            int e2 = e - G_*Kin;
            int gp = e2 / H_, col = e2 - gp*H_;
            int j = gp >> 2, q = gp & 3;
            g_Whh[gp*H_ + col] = Whh[(q*H_ + j)*H_ + col];
        } else {
            int gp = e - G_*Kin - G_*H_;
            int j = gp >> 2, q = gp & 3;
            g_bias[gp] = bih[q*H_ + j] + bhh[q*H_ + j];
        }
    }
}

__global__ void zero_hc_kernel() {
    int i = blockIdx.x*blockDim.x + threadIdx.x;
    if (i == 0) { g_arrive = 0u; g_release = 0u; }
    if (i < BH_) { g_h[0][i] = 0.f; }
}

// ---------------- precompute GEMM: xp[t,b,g'] = sum_i A[(b,t),i]*Wp[g',i] + bias[g'] ----------------
__global__ __launch_bounds__(256, 2)
void gemm_xp_kernel(const float* __restrict__ X, int K, int mode) {
    __shared__ float As[16][132];
    __shared__ float Bs[16][132];
    const int n0 = blockIdx.x * 128;
    const int m0 = blockIdx.y * 128;
    const int b  = m0 >> 10;          // tiles never cross a batch boundary (128 | 1024)
    const int t0 = m0 & 1023;
    const int tid = threadIdx.x;
    const int ty = tid >> 4, tx = tid & 15;
    const int row0 = ty * 8, col0 = tx * 8;

    unsigned long long accp[8][4];
#pragma unroll
    for (int i = 0; i < 8; i++)
#pragma unroll
        for (int j = 0; j < 4; j++) accp[i][j] = 0ull;

    for (int k0 = 0; k0 < K; k0 += 16) {
        if (mode == 0) {
            const int m4 = (tid & 31) * 4;
            const int kk = tid >> 5;
#pragma unroll
            for (int it = 0; it < 2; it++) {
                int k = kk + it * 8;
                float4 v = *(const float4*)(X + (size_t)b*(I_*T_) + (size_t)(k0+k)*T_ + t0 + m4);
                *(float4*)&As[k][m4] = v;
            }
        } else {
            const int kq = tid & 3;
            const int mm = tid >> 2;
#pragma unroll
            for (int it = 0; it < 2; it++) {
                int m = mm + it * 64;
                float4 v = *(const float4*)(g_y0 + (size_t)(t0+m)*BH_ + (size_t)b*H_ + k0 + kq*4);
                As[kq*4+0][m] = v.x; As[kq*4+1][m] = v.y;
                As[kq*4+2][m] = v.z; As[kq*4+3][m] = v.w;
            }
        }
        {
            const int kq = tid & 3;
            const int nn = tid >> 2;
#pragma unroll
            for (int it = 0; it < 2; it++) {
                int n = nn + it * 64;
                float4 v = *(const float4*)(g_Wih + (size_t)(n0+n)*K + k0 + kq*4);
                Bs[kq*4+0][n] = v.x; Bs[kq*4+1][n] = v.y;
                Bs[kq*4+2][n] = v.z; Bs[kq*4+3][n] = v.w;
            }
        }
        __syncthreads();
#pragma unroll
        for (int k = 0; k < 16; k++) {
            float a[8];
            *(float4*)&a[0] = *(const float4*)&As[k][row0];
            *(float4*)&a[4] = *(const float4*)&As[k][row0+4];
            const ulonglong2 w01 = *(const ulonglong2*)&Bs[k][col0];
            const ulonglong2 w23 = *(const ulonglong2*)&Bs[k][col0+4];
#pragma unroll
            for (int i = 0; i < 8; i++) {
                unsigned long long ad;
                asm("mov.b64 %0, {%1,%1};" : "=l"(ad) : "f"(a[i]));
                asm("fma.rn.f32x2 %0, %1, %2, %0;" : "+l"(accp[i][0]) : "l"(ad), "l"(w01.x));
                asm("fma.rn.f32x2 %0, %1, %2, %0;" : "+l"(accp[i][1]) : "l"(ad), "l"(w01.y));
                asm("fma.rn.f32x2 %0, %1, %2, %0;" : "+l"(accp[i][2]) : "l"(ad), "l"(w23.x));
                asm("fma.rn.f32x2 %0, %1, %2, %0;" : "+l"(accp[i][3]) : "l"(ad), "l"(w23.y));
            }
        }
        __syncthreads();
    }
    float bw[8];
#pragma unroll
    for (int j = 0; j < 8; j++) bw[j] = g_bias[n0 + col0 + j];
#pragma unroll
    for (int i = 0; i < 8; i++) {
        float o[8];
#pragma unroll
        for (int j = 0; j < 4; j++)
            asm("mov.b64 {%0,%1}, %2;" : "=f"(o[2*j]), "=f"(o[2*j+1]) : "l"(accp[i][j]));
        int t = t0 + row0 + i;
        size_t base = (size_t)t*BG_ + (size_t)b*G_ + n0 + col0;
        float4 v0 = make_float4(o[0]+bw[0], o[1]+bw[1], o[2]+bw[2], o[3]+bw[3]);
        float4 v1 = make_float4(o[4]+bw[4], o[5]+bw[5], o[6]+bw[6], o[7]+bw[7]);
        *(float4*)&g_xp[base]     = v0;
        *(float4*)&g_xp[base + 4] = v1;
    }
}

// ---------------- persistent recurrence: all 1024 steps in ONE kernel ----------------
// grid = 128 blocks x 512 threads (16 warps/SM). Block bx owns hidden units
// [4*bx,4*bx+4) = 16 gate-interleaved columns.
// FFMA2 pairs along K: acc.lo sums even-k terms, acc.hi odd-k; halves added at end.
// -> W stored plain [col][k] (32 KB, no duplication); h staged [b][k] with NO
//    transpose (fully coalesced float4 copy), double-buffered 64x64 chunks.
// XOR swizzles keep LDS.128 at wavefront floor:
//   Hs slot = kq ^ ((row>>2)&7),  Ws slot = kq ^ (col&7).
// Thread tile: 4 rows x 4 cols x K-split-8 -> per 4k-block 8 LDS.128 + 32 FFMA2.
// Cell state c lives in a register for the whole sequence.
__global__ __launch_bounds__(512)
void lstm_seq_kernel(int layer, float* __restrict__ dout) {
    extern __shared__ unsigned char sm[];
    float* Ws  = (float*)sm;                       // [16][512] swizzled, 32 KB
    float* Hs0 = (float*)(sm + 32768);             // [64][64] chunk buffer, 16 KB
    float* Hs1 = (float*)(sm + 32768 + 16384);     // second buffer, 16 KB
    float* Gs  = (float*)(sm + 65536);             // [8][64][20], 40 KB
    const int tid = threadIdx.x;
    const int bx  = blockIdx.x;
    const int n0  = bx * 16;
    // compute tiling
    const int rg = tid & 15;
    const int cg = (tid >> 4) & 3;
    const int ks = tid >> 6;            // 0..7 : k-slice (8 k per 64-chunk)
    const int r0 = rg * 4;
    const int c0 = cg * 4;
    const int hswz = rg & 7;            // h-read swizzle (rows r0..r0+3 share row>>2 = rg)
    // staging: 8 threads per batch row, 2 float4 slots each
    const int sb = tid >> 3;            // 0..63
    const int st = tid & 7;             // slot base; slots st and st+8
    const int sswz = (sb >> 2) & 7;
    // pointwise (tid < 256)
    const int pb = tid >> 2, pu = tid & 3, pj = bx*4 + pu;
    const int csw = (cg ^ (rg & 3)) * 4;           // Gs write col slot
    const int prw = (pu ^ ((pb >> 2) & 3)) * 4;    // Gs read col slot

    // Load Ws (plain weights, k-swizzled) once.
    for (int idx = tid; idx < 16*128; idx += 512) {
        int c = idx >> 7, kq = idx & 127;
        float4 v = *(const float4*)(g_Whh + (size_t)(n0 + c)*H_ + kq*4);
        *(float4*)(Ws + c*512 + ((kq ^ (c & 7)) << 2)) = v;
    }

    float c_reg = 0.f;

    for (int t = 0; t < T_; t++) {
        const float* __restrict__ h_in  = g_h[t & 1];
        float*       __restrict__ h_out = g_h[(t & 1) ^ 1];

        float4 xpv = make_float4(0.f, 0.f, 0.f, 0.f);
        if (tid < 256)
            xpv = __ldcg((const float4*)(g_xp + (size_t)t*BG_ + (size_t)pb*G_ + n0 + pu*4));

        unsigned long long acc[4][4];
#pragma unroll
        for (int i = 0; i < 4; i++)
#pragma unroll
            for (int j = 0; j < 4; j++) acc[i][j] = 0ull;

        // stage chunk 0, prefetch chunk 1
        float4 pf0 = __ldcg((const float4*)(h_in + sb*H_ + st*4));
        float4 pf1 = __ldcg((const float4*)(h_in + sb*H_ + (st+8)*4));
        *(float4*)(Hs0 + sb*64 + ((st       ^ sswz) << 2)) = pf0;
        *(float4*)(Hs0 + sb*64 + (((st + 8) ^ sswz) << 2)) = pf1;
        pf0 = __ldcg((const float4*)(h_in + sb*H_ + 64 + st*4));
        pf1 = __ldcg((const float4*)(h_in + sb*H_ + 64 + (st+8)*4));
        __syncthreads();

        for (int ck = 0; ck < 8; ck++) {
            const float* cur = (ck & 1) ? Hs1 : Hs0;
            if (ck < 7) {
                float* nxt = (ck & 1) ? Hs0 : Hs1;
                *(float4*)(nxt + sb*64 + ((st       ^ sswz) << 2)) = pf0;
                *(float4*)(nxt + sb*64 + (((st + 8) ^ sswz) << 2)) = pf1;
                if (ck < 6) {
                    pf0 = __ldcg((const float4*)(h_in + sb*H_ + (ck+2)*64 + st*4));
                    pf1 = __ldcg((const float4*)(h_in + sb*H_ + (ck+2)*64 + (st+8)*4));
                }
            }
#pragma unroll
            for (int kb = 0; kb < 2; kb++) {
                const int lq = ks*2 + kb;                 // chunk-local float4 slot
                const int gq = ck*16 + lq;                // global float4 slot
                ulonglong2 hp[4];
#pragma unroll
                for (int i = 0; i < 4; i++)
                    hp[i] = *(const ulonglong2*)(cur + (r0+i)*64 + ((lq ^ hswz) << 2));
#pragma unroll
                for (int j = 0; j < 4; j++) {
                    const int c = c0 + j;
                    ulonglong2 wp = *(const ulonglong2*)(Ws + c*512 + ((gq ^ (c & 7)) << 2));
                    asm("fma.rn.f32x2 %0, %1, %2, %0;" : "+l"(acc[0][j]) : "l"(hp[0].x), "l"(wp.x));
                    asm("fma.rn.f32x2 %0, %1, %2, %0;" : "+l"(acc[1][j]) : "l"(hp[1].x), "l"(wp.x));
                    asm("fma.rn.f32x2 %0, %1, %2, %0;" : "+l"(acc[2][j]) : "l"(hp[2].x), "l"(wp.x));
                    asm("fma.rn.f32x2 %0, %1, %2, %0;" : "+l"(acc[3][j]) : "l"(hp[3].x), "l"(wp.x));
                    asm("fma.rn.f32x2 %0, %1, %2, %0;" : "+l"(acc[0][j]) : "l"(hp[0].y), "l"(wp.y));
                    asm("fma.rn.f32x2 %0, %1, %2, %0;" : "+l"(acc[1][j]) : "l"(hp[1].y), "l"(wp.y));
                    asm("fma.rn.f32x2 %0, %1, %2, %0;" : "+l"(acc[2][j]) : "l"(hp[2].y), "l"(wp.y));
                    asm("fma.rn.f32x2 %0, %1, %2, %0;" : "+l"(acc[3][j]) : "l"(hp[3].y), "l"(wp.y));
                }
            }
            __syncthreads();
        }

        // park partial sums (add the even/odd halves)
#pragma unroll
        for (int i = 0; i < 4; i++) {
            float4 v;
            float lo, hi;
            asm("mov.b64 {%0,%1}, %2;" : "=f"(lo), "=f"(hi) : "l"(acc[i][0])); v.x = lo + hi;
            asm("mov.b64 {%0,%1}, %2;" : "=f"(lo), "=f"(hi) : "l"(acc[i][1])); v.y = lo + hi;
            asm("mov.b64 {%0,%1}, %2;" : "=f"(lo), "=f"(hi) : "l"(acc[i][2])); v.z = lo + hi;
            asm("mov.b64 {%0,%1}, %2;" : "=f"(lo), "=f"(hi) : "l"(acc[i][3])); v.w = lo + hi;
            *(float4*)(Gs + ks*1280 + (r0+i)*20 + csw) = v;
        }
        __syncthreads();

        if (tid < 256) {   // pointwise: reduce 8 k-slices, LSTM cell; c in register
            float4 s = xpv;
#pragma unroll
            for (int q = 0; q < 8; q++) {
                float4 g = *(const float4*)(Gs + q*1280 + pb*20 + prw);
                s.x += g.x; s.y += g.y; s.z += g.z; s.w += g.w;
            }
            float iv = sig_ap(s.x);
            float fv = sig_ap(s.y);
            float gv = tanh_ap(s.z);
            float ov = sig_ap(s.w);
            c_reg = fv * c_reg + iv * gv;
            float hv = ov * tanh_ap(c_reg);
            __stcg(h_out + pb*H_ + pj, hv);
            if (layer == 0) g_y0[(size_t)t*BH_ + pb*H_ + pj] = hv;
            else            dout[(size_t)pb*(T_*H_) + (size_t)t*H_ + pj] = hv;
            if (t == T_-1) {
                size_t base = (size_t)B_ * T_ * H_;
                dout[base + (size_t)layer*BH_     + pb*H_ + pj] = hv;     // hT
                dout[base + (size_t)(2+layer)*BH_ + pb*H_ + pj] = c_reg;  // cT
            }
        }

        // grid barrier: all h_out writes visible before any block starts step t+1
        if (t < T_-1) {
            __threadfence();
            __syncthreads();
            if (tid == 0) {
                unsigned target = (unsigned)(t + 1);
                unsigned prev = atomicAdd(&g_arrive, 1u);
                if (prev == target*128u - 1u) {
                    atomicExch(&g_release, target);
                } else {
                    while (*((volatile unsigned*)&g_release) < target) { }
                }
            }
            __syncthreads();
        }
    }
}

#define DYN_SMEM (32768 + 32768 + 40960)

extern "C" void kernel_launch(void* const* d_in, const int* in_sizes, int n_in,
                              void* d_out, int out_size) {
    const float* x    = (const float*)d_in[0];
    const float* Wih0 = (const float*)d_in[1];
    const float* Whh0 = (const float*)d_in[2];
    const float* bih0 = (const float*)d_in[3];
    const float* bhh0 = (const float*)d_in[4];
    const float* Wih1 = (const float*)d_in[5];
    const float* Whh1 = (const float*)d_in[6];
    const float* bih1 = (const float*)d_in[7];
    const float* bhh1 = (const float*)d_in[8];
    float* out = (float*)d_out;

    cudaFuncSetAttribute(lstm_seq_kernel,
                         cudaFuncAttributeMaxDynamicSharedMemorySize, DYN_SMEM);

    // ---- layer 0 ----
    permute_kernel<<<2048, 256>>>(Wih0, Whh0, bih0, bhh0, I_);
    gemm_xp_kernel<<<dim3(16, 512), 256>>>(x, I_, 0);
    zero_hc_kernel<<<(BH_ + 255) / 256, 256>>>();
    lstm_seq_kernel<<<128, 512, DYN_SMEM>>>(0, out);

    // ---- layer 1 ----
    permute_kernel<<<2048, 256>>>(Wih1, Whh1, bih1, bhh1, H_);
    gemm_xp_kernel<<<dim3(16, 512), 256>>>(nullptr, H_, 1);
    zero_hc_kernel<<<(BH_ + 255) / 256, 256>>>();
    lstm_seq_kernel<<<128, 512, DYN_SMEM>>>(1, out);
}